// round 8
// baseline (speedup 1.0000x reference)
#include <cuda_runtime.h>
#include <math.h>

#define KKEY   2048
#define CFEAT  128
#define M_GRID 216
#define NPROP  48
#define NPTS   (NPROP*M_GRID)      // 10368 per batch
#define NTOT   (2*NPTS)            // 20736
#define QDIM   (128*M_GRID)        // 27648
#define KSPLIT 108
#define KCHUNK 256

typedef unsigned long long ull;

__device__ __forceinline__ ull pack2(float lo, float hi) {
    ull r; asm("mov.b64 %0, {%1, %2};" : "=l"(r) : "f"(lo), "f"(hi)); return r;
}
__device__ __forceinline__ ull ffma2(ull a, ull b, ull c) {
    ull d; asm("fma.rn.f32x2 %0, %1, %2, %3;" : "=l"(d) : "l"(a), "l"(b), "l"(c)); return d;
}
__device__ __forceinline__ float2 unpack2(ull v) {
    float2 f; asm("mov.b64 {%0, %1}, %2;" : "=f"(f.x), "=f"(f.y) : "l"(v)); return f;
}
__device__ __forceinline__ unsigned f2tf32(float v) {
    unsigned u; asm("cvt.rna.tf32.f32 %0, %1;" : "=r"(u) : "f"(v)); return u;
}
__device__ __forceinline__ void mma_tf32(float d[4], const unsigned a0, const unsigned a1,
                                         const unsigned a2, const unsigned a3,
                                         const unsigned b0, const unsigned b1) {
    asm("mma.sync.aligned.m16n8k8.row.col.f32.tf32.tf32.f32 "
        "{%0,%1,%2,%3}, {%4,%5,%6,%7}, {%8,%9}, {%0,%1,%2,%3};"
        : "+f"(d[0]), "+f"(d[1]), "+f"(d[2]), "+f"(d[3])
        : "r"(a0), "r"(a1), "r"(a2), "r"(a3), "r"(b0), "r"(b1));
}

// ---------------- scratch ----------------
__device__ float  g_new_xyz[NTOT*3];
__device__ float  g_pre[2*2*KKEY*64];        // [scale][b][k][interleaved o]
__device__ float4 g_rel1[NTOT*32];           // {rx,ry,rz, bitcast k}
__device__ float4 g_rel0[NTOT*16];
__device__ float  g_pooled[2*NPROP*QDIM];    // 96 x 27648, q = co*216+mm
__device__ float  g_partial[KSPLIT*96*256];

// ---------------- kernel A ----------------
__global__ void __launch_bounds__(256) kA(const float* __restrict__ prop,
                                          const float* __restrict__ gnoise) {
    int t = blockIdx.x*256 + threadIdx.x;
    if (t >= NTOT) return;
    int b = t / NPTS, r = t % NPTS;
    int n = r / M_GRID, mm = r % M_GRID;
    const float* p = prop + (size_t)(b*NPROP + n)*7;
    const float* g = gnoise + ((size_t)(b*NPROP + n)*M_GRID + mm)*3;
    float gx = g[0]*p[3], gy = g[1]*p[4], gz = g[2]*p[5];
    float c = cosf(p[6]), s = sinf(p[6]);
    float* o = g_new_xyz + (size_t)t*3;
    o[0] = c*gx - s*gy + p[0];
    o[1] = s*gx + c*gy + p[1];
    o[2] = gz + p[2];
}

// ---------------- kernel B: pre[k][o] = W0[:,3:] . feats[:,k] ----------------
__global__ void __launch_bounds__(256) kB(const float* __restrict__ feats,
                                          const float* __restrict__ w0,
                                          const float* __restrict__ w1) {
    __shared__ float Ws[CFEAT*64];
    __shared__ float fs[CFEAT*32];
    int sb = blockIdx.y; int sc = sb >> 1, b = sb & 1;
    const float* W = sc ? w1 : w0;
    for (int i = threadIdx.x; i < CFEAT*64; i += 256) {
        int c = i >> 6, o = i & 63;
        Ws[i] = W[o*131 + 3 + c];
    }
    int kbase = blockIdx.x * 32;
    const float* fb = feats + (size_t)b*CFEAT*KKEY + kbase;
    for (int i = threadIdx.x; i < CFEAT*8; i += 256) {
        int c = i >> 3, q = i & 7;
        *(float4*)(fs + c*32 + q*4) = *(const float4*)(fb + (size_t)c*KKEY + q*4);
    }
    __syncthreads();

    int o  = threadIdx.x & 63;
    int kk = threadIdx.x >> 6;
    ull acc0 = 0, acc1 = 0, acc2 = 0, acc3 = 0;
    #pragma unroll 4
    for (int c = 0; c < CFEAT; c++) {
        float w = Ws[c*64 + o];
        ull wd = pack2(w, w);
        const ull* f = (const ull*)(fs + c*32 + kk*8);
        acc0 = ffma2(wd, f[0], acc0);
        acc1 = ffma2(wd, f[1], acc1);
        acc2 = ffma2(wd, f[2], acc2);
        acc3 = ffma2(wd, f[3], acc3);
    }
    size_t base = ((size_t)(sc*2 + b)*KKEY + kbase + kk*8) << 6;
    int oi = ((o & 31) << 1) + (o >> 5);
    float2 u;
    u = unpack2(acc0); g_pre[base + oi] = u.x; g_pre[base + 64 + oi] = u.y;
    u = unpack2(acc1); g_pre[base + 128 + oi] = u.x; g_pre[base + 192 + oi] = u.y;
    u = unpack2(acc2); g_pre[base + 256 + oi] = u.x; g_pre[base + 320 + oi] = u.y;
    u = unpack2(acc3); g_pre[base + 384 + oi] = u.x; g_pre[base + 448 + oi] = u.y;
}

// ---------------- kernel Q: ball query -> padded idx + rel coords ----------
__global__ void __launch_bounds__(256) kQ(const float* __restrict__ kxyzg) {
    __shared__ float kp[KKEY*3];               // interleaved xyz
    __shared__ int idx1s[8][32], idx0s[8][16];

    const int b = blockIdx.x / 1296;
    const float* kb = kxyzg + (size_t)b*KKEY*3;
    for (int i = threadIdx.x; i < KKEY*3; i += 256) kp[i] = kb[i];
    __syncthreads();

    const int w = threadIdx.x >> 5, lane = threadIdx.x & 31;
    const int p = blockIdx.x*8 + w;
    const float px = g_new_xyz[(size_t)p*3], py = g_new_xyz[(size_t)p*3+1],
                pz = g_new_xyz[(size_t)p*3+2];
    const float pn = fmaf(px,px, fmaf(py,py, pz*pz));

    const float R0 = 0.8f*0.8f, R1 = 1.6f*1.6f;
    int* l1 = idx1s[w];
    int* l0 = idx0s[w];
    int c0 = 0, c1 = 0;
    const unsigned lt = (1u << lane) - 1u;
    for (int base = 0; base < KKEY; base += 32) {
        int k = base + lane;
        float kx = kp[3*k], ky = kp[3*k+1], kz = kp[3*k+2];
        float kn  = fmaf(kx,kx, fmaf(ky,ky, kz*kz));
        float dot = fmaf(px,kx, fmaf(py,ky, pz*kz));
        float d2  = fmaf(-2.f, dot, pn + kn);
        bool v1 = d2 < R1, v0 = d2 < R0;
        unsigned m1 = __ballot_sync(0xffffffffu, v1);
        unsigned m0 = __ballot_sync(0xffffffffu, v0);
        if (c1 < 32 && m1) {
            if (v1) { int rk = c1 + __popc(m1 & lt); if (rk < 32) l1[rk] = k; }
            c1 = min(32, c1 + __popc(m1));
        }
        if (c0 < 16 && m0) {
            if (v0) { int rk = c0 + __popc(m0 & lt); if (rk < 16) l0[rk] = k; }
            c0 = min(16, c0 + __popc(m0));
        }
        if (c0 >= 16 && c1 >= 32) break;
    }
    __syncwarp();
    if (c1 == 0) { if (lane == 0) l1[0] = 0; c1 = 1; }
    if (c0 == 0) { if (lane == 0) l0[0] = 0; c0 = 1; }
    __syncwarp();
    {
        int f1 = l1[0], f0 = l0[0];
        if (lane >= c1) l1[lane] = f1;
        if (lane < 16 && lane >= c0) l0[lane] = f0;
    }
    __syncwarp();

    {
        int k = l1[lane];
        g_rel1[(size_t)p*32 + lane] =
            make_float4(kp[3*k]-px, kp[3*k+1]-py, kp[3*k+2]-pz, __int_as_float(k));
        if (lane < 16) {
            int k0 = l0[lane];
            g_rel0[(size_t)p*16 + lane] =
                make_float4(kp[3*k0]-px, kp[3*k0+1]-py, kp[3*k0+2]-pz, __int_as_float(k0));
        }
    }
}

// ---------------- kernel C2: 1 pt/warp, packed hw + LDS.64 a-frags ----------
// 384 threads = 12 warps = 12 points/block.
// k-permutation: logical o (va) -> k' = (o>>2)*8 + (o&3); o+32 (vb) -> k'+4.
// Memory address of k' within a row: addr(kt*8+tig+4*b2) = kt*8 + tig*2 + b2.
// So layer-0 writes (va,vb) with one STS.64 at row*72 + (lane>>2)*8 + (lane&3)*2,
// and the MMA a-frag (a0,a2)/(a1,a3) are adjacent 8B pairs -> LDS.64.
// b-table: slot (kt,nt,lane:gid,tig) holds W1[nt*8+gid][kt*4+tig (+32)].
// dyn smem words:
//  wpk[2][8kt][8nt][32] uint2            0     .. 8192
//  wxyz[2][3][64]                        8192  .. 8576
//  b0s[128]                              8576  .. 8704
//  b1s[128]                              8704  .. 8832
//  hw[12 warps][16 rows][72]             8832  .. 22656
#define KC2_SMEM_WORDS 22656
#define OFF2_WXYZ 8192
#define OFF2_B0   8576
#define OFF2_B1   8704
#define OFF2_HW   8832
#define HW_PITCH  72

__global__ void __launch_bounds__(384, 2) kC2(
    const float* __restrict__ w00, const float* __restrict__ b00,
    const float* __restrict__ w01, const float* __restrict__ b01,
    const float* __restrict__ w10, const float* __restrict__ b10,
    const float* __restrict__ w11, const float* __restrict__ b11)
{
    extern __shared__ float sm[];
    uint2*    wpk  = (uint2*)sm;               // [sc][kt][nt][lane]
    float*    wxyz = sm + OFF2_WXYZ;
    float*    b0s  = sm + OFF2_B0;
    float*    b1s  = sm + OFF2_B1;
    unsigned* hwg  = (unsigned*)(sm + OFF2_HW);

    // b-table under the k-permutation: b0 <- j = kt*4+tig, b1 <- j+32
    for (int i = threadIdx.x; i < 2*8*8*32; i += 384) {
        int lane2 = i & 31, nt = (i >> 5) & 7, kt = (i >> 8) & 7, sc = i >> 11;
        int gid2 = lane2 >> 2, tig2 = lane2 & 3;
        const float* W1 = sc ? w11 : w01;
        int o = nt*8 + gid2;
        int j = kt*4 + tig2;
        wpk[i] = make_uint2(f2tf32(W1[o*64 + j]), f2tf32(W1[o*64 + j + 32]));
    }
    for (int i = threadIdx.x; i < 2*3*64; i += 384) {
        int sc = i / 192, t = i % 192, d = t / 64, o = t % 64;
        wxyz[i] = (sc ? w10 : w00)[o*131 + d];
    }
    if (threadIdx.x < 256) {
        int sc = (threadIdx.x >> 6) & 1, o = threadIdx.x & 63;
        if (threadIdx.x < 128) b0s[threadIdx.x] = (sc ? b10 : b00)[o];
        else                   b1s[threadIdx.x - 128] = (sc ? b11 : b01)[o];
    }
    __syncthreads();

    const int w = threadIdx.x >> 5, lane = threadIdx.x & 31;
    const int gid = lane >> 2, tig = lane & 3;
    const int p  = blockIdx.x*12 + w;
    const int b  = p / NPTS;
    const int rp = p % NPTS;
    const int n  = rp / M_GRID, mm = rp % M_GRID;

    unsigned* hw = hwg + w*16*HW_PITCH;        // [row 0..15][addr 0..63]
    const int sts_off = (lane >> 2)*8 + (lane & 3)*2;

    #pragma unroll
    for (int sc = 0; sc < 2; sc++) {
        const int NPASS = sc ? 2 : 1;
        const float* preb = g_pre + ((size_t)(sc*2 + b)*KKEY << 6);
        const uint2* wps = wpk + sc*2048;
        const float* wx = wxyz + sc*192;
        const float bias0a = b0s[sc*64 + lane],  bias0b = b0s[sc*64 + lane + 32];
        const float wxa0 = wx[lane],    wxa1 = wx[64+lane],  wxa2 = wx[128+lane];
        const float wxb0 = wx[lane+32], wxb1 = wx[96+lane],  wxb2 = wx[160+lane];

        float cm0[8], cm1[8];
        #pragma unroll
        for (int nt = 0; nt < 8; nt++) { cm0[nt] = -3.4e38f; cm1[nt] = -3.4e38f; }

        for (int pass = 0; pass < NPASS; pass++) {
            const float4* relb = sc
                ? (g_rel1 + (size_t)p*32 + pass*16)
                : (g_rel0 + (size_t)p*16);
            // ---- layer 0: 16 samples -> hw (broadcast rel, packed STS.64) ----
            #pragma unroll
            for (int s0 = 0; s0 < 16; s0 += 4) {
                float4 rv[4];
                float2 pr[4];
                #pragma unroll
                for (int s = 0; s < 4; s++) {
                    rv[s] = __ldg(relb + s0 + s);      // uniform addr -> broadcast
                    int k = __float_as_int(rv[s].w);
                    pr[s] = *(const float2*)(preb + ((size_t)k << 6) + (lane << 1));
                }
                #pragma unroll
                for (int s = 0; s < 4; s++) {
                    float va = pr[s].x + bias0a;
                    va = fmaf(rv[s].x, wxa0, va);
                    va = fmaf(rv[s].y, wxa1, va);
                    va = fmaf(rv[s].z, wxa2, va);
                    float vb = pr[s].y + bias0b;
                    vb = fmaf(rv[s].x, wxb0, vb);
                    vb = fmaf(rv[s].y, wxb1, vb);
                    vb = fmaf(rv[s].z, wxb2, vb);
                    *(uint2*)(hw + (s0+s)*HW_PITCH + sts_off) =
                        make_uint2(f2tf32(fmaxf(va, 0.f)), f2tf32(fmaxf(vb, 0.f)));
                }
            }
            __syncwarp();

            // ---- layer 1 MMA: a-frags as 2x LDS.64 per kt ----
            float acc[8][4];
            #pragma unroll
            for (int nt = 0; nt < 8; nt++)
                acc[nt][0] = acc[nt][1] = acc[nt][2] = acc[nt][3] = 0.f;
            #pragma unroll
            for (int kt = 0; kt < 8; kt++) {
                uint2 alo = *(const uint2*)(hw + gid*HW_PITCH + kt*8 + tig*2);
                uint2 ahi = *(const uint2*)(hw + (gid+8)*HW_PITCH + kt*8 + tig*2);
                const uint2* wrow = wps + kt*256 + lane;
                #pragma unroll
                for (int nt = 0; nt < 8; nt++) {
                    uint2 bb = wrow[nt*32];
                    mma_tf32(acc[nt], alo.x, ahi.x, alo.y, ahi.y, bb.x, bb.y);
                }
            }
            #pragma unroll
            for (int nt = 0; nt < 8; nt++) {
                cm0[nt] = fmaxf(cm0[nt], fmaxf(acc[nt][0], acc[nt][2]));
                cm1[nt] = fmaxf(cm1[nt], fmaxf(acc[nt][1], acc[nt][3]));
            }
            __syncwarp();
        }

        // reduce across row-groups (lane bits 2..4)
        #pragma unroll
        for (int off = 4; off <= 16; off <<= 1) {
            #pragma unroll
            for (int nt = 0; nt < 8; nt++) {
                cm0[nt] = fmaxf(cm0[nt], __shfl_xor_sync(0xffffffffu, cm0[nt], off));
                cm1[nt] = fmaxf(cm1[nt], __shfl_xor_sync(0xffffffffu, cm1[nt], off));
            }
        }
        size_t rowb = (size_t)(b*NPROP + n)*QDIM + (size_t)sc*64*M_GRID + mm;
        if (gid == 0) {
            #pragma unroll
            for (int nt = 0; nt < 8; nt++) {
                int o0 = nt*8 + tig*2;
                float v0 = fmaxf(cm0[nt] + b1s[sc*64 + o0],     0.f);
                float v1 = fmaxf(cm1[nt] + b1s[sc*64 + o0 + 1], 0.f);
                g_pooled[rowb + (size_t)o0*M_GRID]     = v0;
                g_pooled[rowb + (size_t)(o0+1)*M_GRID] = v1;
            }
        }
    }
}

// ---------------- kernel D: K-split GEMM, 4x8 thread tile -------------------
#define KD_KT 16
#define XSP 36
#define WSP 260
__global__ void __launch_bounds__(256) kD(const float* __restrict__ w0) {
    __shared__ float xs[2][KD_KT*XSP];
    __shared__ float ws[2][KD_KT*WSP];
    const int tid = threadIdx.x;
    const int tx = tid & 31, ty = tid >> 5;
    const int rowbase = blockIdx.y * 32;
    const int kg0 = blockIdx.z * KCHUNK;

    const int xrow = tid >> 3, xk = (tid & 7) << 1;
    const int wcol = tid >> 2, wk = (tid & 3) << 2;

    const float* xg = g_pooled + (size_t)(rowbase + xrow)*QDIM + kg0 + xk;
    const float* wg0 = w0 + (size_t)(wcol      )*QDIM + kg0 + wk;
    const float* wg1 = w0 + (size_t)(wcol +  64)*QDIM + kg0 + wk;
    const float* wg2 = w0 + (size_t)(wcol + 128)*QDIM + kg0 + wk;
    const float* wg3 = w0 + (size_t)(wcol + 192)*QDIM + kg0 + wk;

    float2 xv = *(const float2*)xg;
    float4 wv0 = *(const float4*)wg0;
    float4 wv1 = *(const float4*)wg1;
    float4 wv2 = *(const float4*)wg2;
    float4 wv3 = *(const float4*)wg3;

    float acc[4][8] = {};
    const int NT = KCHUNK / KD_KT;      // 16
    for (int t = 0; t < NT; t++) {
        float* xsc = xs[t & 1];
        float* wsc = ws[t & 1];
        xsc[(xk  )*XSP + xrow] = xv.x;
        xsc[(xk+1)*XSP + xrow] = xv.y;
        #pragma unroll
        for (int j = 0; j < 4; j++) {
            wsc[(wk+j)*WSP + wcol      ] = ((const float*)&wv0)[j];
            wsc[(wk+j)*WSP + wcol +  64] = ((const float*)&wv1)[j];
            wsc[(wk+j)*WSP + wcol + 128] = ((const float*)&wv2)[j];
            wsc[(wk+j)*WSP + wcol + 192] = ((const float*)&wv3)[j];
        }
        __syncthreads();
        if (t + 1 < NT) {
            int d = (t + 1) * KD_KT;
            xv  = *(const float2*)(xg + d);
            wv0 = *(const float4*)(wg0 + d);
            wv1 = *(const float4*)(wg1 + d);
            wv2 = *(const float4*)(wg2 + d);
            wv3 = *(const float4*)(wg3 + d);
        }
        #pragma unroll
        for (int kk = 0; kk < KD_KT; kk++) {
            float4 xq = *(const float4*)(xsc + kk*XSP + ty*4);
            float4 wa = *(const float4*)(wsc + kk*WSP + tx*4);
            float4 wb = *(const float4*)(wsc + kk*WSP + 128 + tx*4);
            const float xr[4] = {xq.x, xq.y, xq.z, xq.w};
            const float wc[8] = {wa.x, wa.y, wa.z, wa.w, wb.x, wb.y, wb.z, wb.w};
            #pragma unroll
            for (int i = 0; i < 4; i++)
                #pragma unroll
                for (int j = 0; j < 8; j++)
                    acc[i][j] = fmaf(xr[i], wc[j], acc[i][j]);
        }
        __syncthreads();
    }
    #pragma unroll
    for (int i = 0; i < 4; i++) {
        int row = rowbase + ty*4 + i;
        float* pp = g_partial + ((size_t)blockIdx.z*96 + row)*256;
        *(float4*)(pp + tx*4)       = make_float4(acc[i][0], acc[i][1], acc[i][2], acc[i][3]);
        *(float4*)(pp + 128 + tx*4) = make_float4(acc[i][4], acc[i][5], acc[i][6], acc[i][7]);
    }
}

// ---------------- kernel E: reduce + relu + 256x256 GEMM + relu ------------
__global__ void __launch_bounds__(256) kE(const float* __restrict__ rb0,
                                          const float* __restrict__ rw1,
                                          const float* __restrict__ rb1,
                                          float* __restrict__ out) {
    __shared__ float h2s[256];
    __shared__ float w1s[256*33];
    const int row = blockIdx.x;
    const int o = threadIdx.x;
    float s = rb0[o];
    #pragma unroll 4
    for (int ks = 0; ks < KSPLIT; ks++)
        s += g_partial[((size_t)ks*96 + row)*256 + o];
    h2s[o] = fmaxf(s, 0.f);
    __syncthreads();

    float acc = rb1[o];
    for (int jt = 0; jt < 256; jt += 32) {
        for (int i = threadIdx.x; i < 8192; i += 256) {
            int oo = i >> 5, jj = i & 31;
            w1s[oo*33 + jj] = rw1[(size_t)oo*256 + jt + jj];
        }
        __syncthreads();
        #pragma unroll
        for (int jj = 0; jj < 32; jj++)
            acc = fmaf(h2s[jt + jj], w1s[o*33 + jj], acc);
        __syncthreads();
    }
    out[(size_t)row*256 + o] = fmaxf(acc, 0.f);
}

// ---------------- launch ----------------
extern "C" void kernel_launch(void* const* d_in, const int* in_sizes, int n_in,
                              void* d_out, int out_size) {
    const float* proposals = (const float*)d_in[0];
    const float* kxyz      = (const float*)d_in[1];
    const float* kfeat     = (const float*)d_in[2];
    const float* gnoise    = (const float*)d_in[3];
    const float* w00 = (const float*)d_in[4];
    const float* b00 = (const float*)d_in[5];
    const float* w01 = (const float*)d_in[6];
    const float* b01 = (const float*)d_in[7];
    const float* w10 = (const float*)d_in[8];
    const float* b10 = (const float*)d_in[9];
    const float* w11 = (const float*)d_in[10];
    const float* b11 = (const float*)d_in[11];
    const float* rw0 = (const float*)d_in[12];
    const float* rb0 = (const float*)d_in[13];
    const float* rw1 = (const float*)d_in[14];
    const float* rb1 = (const float*)d_in[15];
    float* out = (float*)d_out;

    cudaFuncSetAttribute(kC2, cudaFuncAttributeMaxDynamicSharedMemorySize,
                         KC2_SMEM_WORDS * 4);

    kA<<<(NTOT + 255)/256, 256>>>(proposals, gnoise);
    kB<<<dim3(KKEY/32, 4), 256>>>(kfeat, w00, w10);
    kQ<<<NTOT/8, 256>>>(kxyz);
    kC2<<<NTOT/12, 384, KC2_SMEM_WORDS * 4>>>(w00, b00, w01, b01,
                                              w10, b10, w11, b11);
    kD<<<dim3(1, 96/32, KSPLIT), 256>>>(rw0);
    kE<<<96, 256>>>(rb0, rw1, rb1, out);
}

// round 9
// speedup vs baseline: 1.5364x; 1.5364x over previous
#include <cuda_runtime.h>
#include <math.h>

#define KKEY   2048
#define CFEAT  128
#define M_GRID 216
#define NPROP  48
#define NPTS   (NPROP*M_GRID)      // 10368 per batch
#define NTOT   (2*NPTS)            // 20736
#define QDIM   (128*M_GRID)        // 27648
#define KSPLIT 108
#define KCHUNK 256

typedef unsigned long long ull;

__device__ __forceinline__ ull pack2(float lo, float hi) {
    ull r; asm("mov.b64 %0, {%1, %2};" : "=l"(r) : "f"(lo), "f"(hi)); return r;
}
__device__ __forceinline__ ull ffma2(ull a, ull b, ull c) {
    ull d; asm("fma.rn.f32x2 %0, %1, %2, %3;" : "=l"(d) : "l"(a), "l"(b), "l"(c)); return d;
}
__device__ __forceinline__ float2 unpack2(ull v) {
    float2 f; asm("mov.b64 {%0, %1}, %2;" : "=f"(f.x), "=f"(f.y) : "l"(v)); return f;
}
__device__ __forceinline__ unsigned f2tf32(float v) {
    unsigned u; asm("cvt.rna.tf32.f32 %0, %1;" : "=r"(u) : "f"(v)); return u;
}
__device__ __forceinline__ void mma_tf32(float d[4], const unsigned a0, const unsigned a1,
                                         const unsigned a2, const unsigned a3,
                                         const unsigned b0, const unsigned b1) {
    asm("mma.sync.aligned.m16n8k8.row.col.f32.tf32.tf32.f32 "
        "{%0,%1,%2,%3}, {%4,%5,%6,%7}, {%8,%9}, {%0,%1,%2,%3};"
        : "+f"(d[0]), "+f"(d[1]), "+f"(d[2]), "+f"(d[3])
        : "r"(a0), "r"(a1), "r"(a2), "r"(a3), "r"(b0), "r"(b1));
}

// ---------------- scratch ----------------
__device__ float  g_new_xyz[NTOT*3];
__device__ float  g_pre[2*2*KKEY*64];        // [scale][b][k][interleaved o]
__device__ float4 g_rel1[NTOT*32];           // {rx,ry,rz, bitcast k}
__device__ float4 g_rel0[NTOT*16];
__device__ float  g_pooled[2*NPROP*QDIM];    // 96 x 27648, q = co*216+mm
__device__ float  g_partial[KSPLIT*96*256];

// ---------------- kernel A ----------------
__global__ void __launch_bounds__(256) kA(const float* __restrict__ prop,
                                          const float* __restrict__ gnoise) {
    int t = blockIdx.x*256 + threadIdx.x;
    if (t >= NTOT) return;
    int b = t / NPTS, r = t % NPTS;
    int n = r / M_GRID, mm = r % M_GRID;
    const float* p = prop + (size_t)(b*NPROP + n)*7;
    const float* g = gnoise + ((size_t)(b*NPROP + n)*M_GRID + mm)*3;
    float gx = g[0]*p[3], gy = g[1]*p[4], gz = g[2]*p[5];
    float c = cosf(p[6]), s = sinf(p[6]);
    float* o = g_new_xyz + (size_t)t*3;
    o[0] = c*gx - s*gy + p[0];
    o[1] = s*gx + c*gy + p[1];
    o[2] = gz + p[2];
}

// ---------------- kernel B: pre[k][o] = W0[:,3:] . feats[:,k] ----------------
__global__ void __launch_bounds__(256) kB(const float* __restrict__ feats,
                                          const float* __restrict__ w0,
                                          const float* __restrict__ w1) {
    __shared__ float Ws[CFEAT*64];
    __shared__ float fs[CFEAT*32];
    int sb = blockIdx.y; int sc = sb >> 1, b = sb & 1;
    const float* W = sc ? w1 : w0;
    for (int i = threadIdx.x; i < CFEAT*64; i += 256) {
        int c = i >> 6, o = i & 63;
        Ws[i] = W[o*131 + 3 + c];
    }
    int kbase = blockIdx.x * 32;
    const float* fb = feats + (size_t)b*CFEAT*KKEY + kbase;
    for (int i = threadIdx.x; i < CFEAT*8; i += 256) {
        int c = i >> 3, q = i & 7;
        *(float4*)(fs + c*32 + q*4) = *(const float4*)(fb + (size_t)c*KKEY + q*4);
    }
    __syncthreads();

    int o  = threadIdx.x & 63;
    int kk = threadIdx.x >> 6;
    ull acc0 = 0, acc1 = 0, acc2 = 0, acc3 = 0;
    #pragma unroll 4
    for (int c = 0; c < CFEAT; c++) {
        float w = Ws[c*64 + o];
        ull wd = pack2(w, w);
        const ull* f = (const ull*)(fs + c*32 + kk*8);
        acc0 = ffma2(wd, f[0], acc0);
        acc1 = ffma2(wd, f[1], acc1);
        acc2 = ffma2(wd, f[2], acc2);
        acc3 = ffma2(wd, f[3], acc3);
    }
    size_t base = ((size_t)(sc*2 + b)*KKEY + kbase + kk*8) << 6;
    int oi = ((o & 31) << 1) + (o >> 5);
    float2 u;
    u = unpack2(acc0); g_pre[base + oi] = u.x; g_pre[base + 64 + oi] = u.y;
    u = unpack2(acc1); g_pre[base + 128 + oi] = u.x; g_pre[base + 192 + oi] = u.y;
    u = unpack2(acc2); g_pre[base + 256 + oi] = u.x; g_pre[base + 320 + oi] = u.y;
    u = unpack2(acc3); g_pre[base + 384 + oi] = u.x; g_pre[base + 448 + oi] = u.y;
}

// ---------------- kernel Q: ball query -> padded idx + rel coords ----------
__global__ void __launch_bounds__(256) kQ(const float* __restrict__ kxyzg) {
    __shared__ float kp[KKEY*3];               // interleaved xyz
    __shared__ int idx1s[8][32], idx0s[8][16];

    const int b = blockIdx.x / 1296;
    const float* kb = kxyzg + (size_t)b*KKEY*3;
    for (int i = threadIdx.x; i < KKEY*3; i += 256) kp[i] = kb[i];
    __syncthreads();

    const int w = threadIdx.x >> 5, lane = threadIdx.x & 31;
    const int p = blockIdx.x*8 + w;
    const float px = g_new_xyz[(size_t)p*3], py = g_new_xyz[(size_t)p*3+1],
                pz = g_new_xyz[(size_t)p*3+2];
    const float pn = fmaf(px,px, fmaf(py,py, pz*pz));

    const float R0 = 0.8f*0.8f, R1 = 1.6f*1.6f;
    int* l1 = idx1s[w];
    int* l0 = idx0s[w];
    int c0 = 0, c1 = 0;
    const unsigned lt = (1u << lane) - 1u;
    for (int base = 0; base < KKEY; base += 32) {
        int k = base + lane;
        float kx = kp[3*k], ky = kp[3*k+1], kz = kp[3*k+2];
        float kn  = fmaf(kx,kx, fmaf(ky,ky, kz*kz));
        float dot = fmaf(px,kx, fmaf(py,ky, pz*kz));
        float d2  = fmaf(-2.f, dot, pn + kn);
        bool v1 = d2 < R1, v0 = d2 < R0;
        unsigned m1 = __ballot_sync(0xffffffffu, v1);
        unsigned m0 = __ballot_sync(0xffffffffu, v0);
        if (c1 < 32 && m1) {
            if (v1) { int rk = c1 + __popc(m1 & lt); if (rk < 32) l1[rk] = k; }
            c1 = min(32, c1 + __popc(m1));
        }
        if (c0 < 16 && m0) {
            if (v0) { int rk = c0 + __popc(m0 & lt); if (rk < 16) l0[rk] = k; }
            c0 = min(16, c0 + __popc(m0));
        }
        if (c0 >= 16 && c1 >= 32) break;
    }
    __syncwarp();
    if (c1 == 0) { if (lane == 0) l1[0] = 0; c1 = 1; }
    if (c0 == 0) { if (lane == 0) l0[0] = 0; c0 = 1; }
    __syncwarp();
    {
        int f1 = l1[0], f0 = l0[0];
        if (lane >= c1) l1[lane] = f1;
        if (lane < 16 && lane >= c0) l0[lane] = f0;
    }
    __syncwarp();

    {
        int k = l1[lane];
        g_rel1[(size_t)p*32 + lane] =
            make_float4(kp[3*k]-px, kp[3*k+1]-py, kp[3*k+2]-pz, __int_as_float(k));
        if (lane < 16) {
            int k0 = l0[lane];
            g_rel0[(size_t)p*16 + lane] =
                make_float4(kp[3*k0]-px, kp[3*k0+1]-py, kp[3*k0+2]-pz, __int_as_float(k0));
        }
    }
}

// ---------------- kernel C2: 1 pt/warp, smem-staged rel + packed frags ------
// 384 threads = 12 warps = 12 points/block.
// rel staged ONCE per point into per-warp smem (2x STS.128), then each sample
// reads it as a uniform LDS.128 broadcast — keeps the pr-gather LDG chain
// short (R6 behavior) while using R8's validated packed STS.64 / LDS.64 frags.
// k-permutation identical to R8 (correctness validated there).
// dyn smem words:
//  wpk[2][8kt][8nt][32] uint2            0     .. 8192
//  wxyz[2][3][64]                        8192  .. 8576
//  b0s[128]                              8576  .. 8704
//  b1s[128]                              8704  .. 8832
//  hw[12 warps][16 rows][72]             8832  .. 22656
//  rel[12 warps][48 float4]              22656 .. 24960
#define KC2_SMEM_WORDS 24960
#define OFF2_WXYZ 8192
#define OFF2_B0   8576
#define OFF2_B1   8704
#define OFF2_HW   8832
#define OFF2_REL  22656
#define HW_PITCH  72

__global__ void __launch_bounds__(384, 2) kC2(
    const float* __restrict__ w00, const float* __restrict__ b00,
    const float* __restrict__ w01, const float* __restrict__ b01,
    const float* __restrict__ w10, const float* __restrict__ b10,
    const float* __restrict__ w11, const float* __restrict__ b11)
{
    extern __shared__ float sm[];
    uint2*    wpk  = (uint2*)sm;               // [sc][kt][nt][lane]
    float*    wxyz = sm + OFF2_WXYZ;
    float*    b0s  = sm + OFF2_B0;
    float*    b1s  = sm + OFF2_B1;
    unsigned* hwg  = (unsigned*)(sm + OFF2_HW);
    float4*   relg = (float4*)(sm + OFF2_REL); // [12 warps][48]

    // b-table under the k-permutation: b0 <- j = kt*4+tig, b1 <- j+32
    for (int i = threadIdx.x; i < 2*8*8*32; i += 384) {
        int lane2 = i & 31, nt = (i >> 5) & 7, kt = (i >> 8) & 7, sc = i >> 11;
        int gid2 = lane2 >> 2, tig2 = lane2 & 3;
        const float* W1 = sc ? w11 : w01;
        int o = nt*8 + gid2;
        int j = kt*4 + tig2;
        wpk[i] = make_uint2(f2tf32(W1[o*64 + j]), f2tf32(W1[o*64 + j + 32]));
    }
    for (int i = threadIdx.x; i < 2*3*64; i += 384) {
        int sc = i / 192, t = i % 192, d = t / 64, o = t % 64;
        wxyz[i] = (sc ? w10 : w00)[o*131 + d];
    }
    if (threadIdx.x < 256) {
        int sc = (threadIdx.x >> 6) & 1, o = threadIdx.x & 63;
        if (threadIdx.x < 128) b0s[threadIdx.x] = (sc ? b10 : b00)[o];
        else                   b1s[threadIdx.x - 128] = (sc ? b11 : b01)[o];
    }
    __syncthreads();

    const int w = threadIdx.x >> 5, lane = threadIdx.x & 31;
    const int gid = lane >> 2, tig = lane & 3;
    const int p  = blockIdx.x*12 + w;
    const int b  = p / NPTS;
    const int rp = p % NPTS;
    const int n  = rp / M_GRID, mm = rp % M_GRID;

    unsigned* hw = hwg + w*16*HW_PITCH;        // [row 0..15][addr 0..63]
    float4*   relw = relg + w*48;              // [0..16): rel0, [16..48): rel1
    const int sts_off = (lane >> 2)*8 + (lane & 3)*2;

    // stage rel once per point (coalesced LDG.128 -> STS.128)
    relw[16 + lane] = g_rel1[(size_t)p*32 + lane];
    if (lane < 16) relw[lane] = g_rel0[(size_t)p*16 + lane];
    __syncwarp();

    #pragma unroll
    for (int sc = 0; sc < 2; sc++) {
        const int NPASS = sc ? 2 : 1;
        const float* preb = g_pre + ((size_t)(sc*2 + b)*KKEY << 6);
        const uint2* wps = wpk + sc*2048;
        const float* wx = wxyz + sc*192;
        const float bias0a = b0s[sc*64 + lane],  bias0b = b0s[sc*64 + lane + 32];
        const float wxa0 = wx[lane],    wxa1 = wx[64+lane],  wxa2 = wx[128+lane];
        const float wxb0 = wx[lane+32], wxb1 = wx[96+lane],  wxb2 = wx[160+lane];

        float cm0[8], cm1[8];
        #pragma unroll
        for (int nt = 0; nt < 8; nt++) { cm0[nt] = -3.4e38f; cm1[nt] = -3.4e38f; }

        for (int pass = 0; pass < NPASS; pass++) {
            const float4* relb = sc ? (relw + 16 + pass*16) : relw;
            // ---- layer 0: 16 samples -> hw (LDS.128 broadcast rel) ----
            #pragma unroll
            for (int s0 = 0; s0 < 16; s0 += 4) {
                float4 rv[4];
                float2 pr[4];
                #pragma unroll
                for (int s = 0; s < 4; s++) {
                    rv[s] = relb[s0 + s];              // uniform LDS.128 broadcast
                    int k = __float_as_int(rv[s].w);
                    pr[s] = *(const float2*)(preb + ((size_t)k << 6) + (lane << 1));
                }
                #pragma unroll
                for (int s = 0; s < 4; s++) {
                    float va = pr[s].x + bias0a;
                    va = fmaf(rv[s].x, wxa0, va);
                    va = fmaf(rv[s].y, wxa1, va);
                    va = fmaf(rv[s].z, wxa2, va);
                    float vb = pr[s].y + bias0b;
                    vb = fmaf(rv[s].x, wxb0, vb);
                    vb = fmaf(rv[s].y, wxb1, vb);
                    vb = fmaf(rv[s].z, wxb2, vb);
                    *(uint2*)(hw + (s0+s)*HW_PITCH + sts_off) =
                        make_uint2(f2tf32(fmaxf(va, 0.f)), f2tf32(fmaxf(vb, 0.f)));
                }
            }
            __syncwarp();

            // ---- layer 1 MMA: a-frags as 2x LDS.64 per kt ----
            float acc[8][4];
            #pragma unroll
            for (int nt = 0; nt < 8; nt++)
                acc[nt][0] = acc[nt][1] = acc[nt][2] = acc[nt][3] = 0.f;
            #pragma unroll
            for (int kt = 0; kt < 8; kt++) {
                uint2 alo = *(const uint2*)(hw + gid*HW_PITCH + kt*8 + tig*2);
                uint2 ahi = *(const uint2*)(hw + (gid+8)*HW_PITCH + kt*8 + tig*2);
                const uint2* wrow = wps + kt*256 + lane;
                #pragma unroll
                for (int nt = 0; nt < 8; nt++) {
                    uint2 bb = wrow[nt*32];
                    mma_tf32(acc[nt], alo.x, ahi.x, alo.y, ahi.y, bb.x, bb.y);
                }
            }
            #pragma unroll
            for (int nt = 0; nt < 8; nt++) {
                cm0[nt] = fmaxf(cm0[nt], fmaxf(acc[nt][0], acc[nt][2]));
                cm1[nt] = fmaxf(cm1[nt], fmaxf(acc[nt][1], acc[nt][3]));
            }
            __syncwarp();
        }

        // reduce across row-groups (lane bits 2..4)
        #pragma unroll
        for (int off = 4; off <= 16; off <<= 1) {
            #pragma unroll
            for (int nt = 0; nt < 8; nt++) {
                cm0[nt] = fmaxf(cm0[nt], __shfl_xor_sync(0xffffffffu, cm0[nt], off));
                cm1[nt] = fmaxf(cm1[nt], __shfl_xor_sync(0xffffffffu, cm1[nt], off));
            }
        }
        size_t rowb = (size_t)(b*NPROP + n)*QDIM + (size_t)sc*64*M_GRID + mm;
        if (gid == 0) {
            #pragma unroll
            for (int nt = 0; nt < 8; nt++) {
                int o0 = nt*8 + tig*2;
                float v0 = fmaxf(cm0[nt] + b1s[sc*64 + o0],     0.f);
                float v1 = fmaxf(cm1[nt] + b1s[sc*64 + o0 + 1], 0.f);
                g_pooled[rowb + (size_t)o0*M_GRID]     = v0;
                g_pooled[rowb + (size_t)(o0+1)*M_GRID] = v1;
            }
        }
    }
}

// ---------------- kernel D: K-split GEMM, 4x8 thread tile -------------------
#define KD_KT 16
#define XSP 36
#define WSP 260
__global__ void __launch_bounds__(256) kD(const float* __restrict__ w0) {
    __shared__ float xs[2][KD_KT*XSP];
    __shared__ float ws[2][KD_KT*WSP];
    const int tid = threadIdx.x;
    const int tx = tid & 31, ty = tid >> 5;
    const int rowbase = blockIdx.y * 32;
    const int kg0 = blockIdx.z * KCHUNK;

    const int xrow = tid >> 3, xk = (tid & 7) << 1;
    const int wcol = tid >> 2, wk = (tid & 3) << 2;

    const float* xg = g_pooled + (size_t)(rowbase + xrow)*QDIM + kg0 + xk;
    const float* wg0 = w0 + (size_t)(wcol      )*QDIM + kg0 + wk;
    const float* wg1 = w0 + (size_t)(wcol +  64)*QDIM + kg0 + wk;
    const float* wg2 = w0 + (size_t)(wcol + 128)*QDIM + kg0 + wk;
    const float* wg3 = w0 + (size_t)(wcol + 192)*QDIM + kg0 + wk;

    float2 xv = *(const float2*)xg;
    float4 wv0 = *(const float4*)wg0;
    float4 wv1 = *(const float4*)wg1;
    float4 wv2 = *(const float4*)wg2;
    float4 wv3 = *(const float4*)wg3;

    float acc[4][8] = {};
    const int NT = KCHUNK / KD_KT;      // 16
    for (int t = 0; t < NT; t++) {
        float* xsc = xs[t & 1];
        float* wsc = ws[t & 1];
        xsc[(xk  )*XSP + xrow] = xv.x;
        xsc[(xk+1)*XSP + xrow] = xv.y;
        #pragma unroll
        for (int j = 0; j < 4; j++) {
            wsc[(wk+j)*WSP + wcol      ] = ((const float*)&wv0)[j];
            wsc[(wk+j)*WSP + wcol +  64] = ((const float*)&wv1)[j];
            wsc[(wk+j)*WSP + wcol + 128] = ((const float*)&wv2)[j];
            wsc[(wk+j)*WSP + wcol + 192] = ((const float*)&wv3)[j];
        }
        __syncthreads();
        if (t + 1 < NT) {
            int d = (t + 1) * KD_KT;
            xv  = *(const float2*)(xg + d);
            wv0 = *(const float4*)(wg0 + d);
            wv1 = *(const float4*)(wg1 + d);
            wv2 = *(const float4*)(wg2 + d);
            wv3 = *(const float4*)(wg3 + d);
        }
        #pragma unroll
        for (int kk = 0; kk < KD_KT; kk++) {
            float4 xq = *(const float4*)(xsc + kk*XSP + ty*4);
            float4 wa = *(const float4*)(wsc + kk*WSP + tx*4);
            float4 wb = *(const float4*)(wsc + kk*WSP + 128 + tx*4);
            const float xr[4] = {xq.x, xq.y, xq.z, xq.w};
            const float wc[8] = {wa.x, wa.y, wa.z, wa.w, wb.x, wb.y, wb.z, wb.w};
            #pragma unroll
            for (int i = 0; i < 4; i++)
                #pragma unroll
                for (int j = 0; j < 8; j++)
                    acc[i][j] = fmaf(xr[i], wc[j], acc[i][j]);
        }
        __syncthreads();
    }
    #pragma unroll
    for (int i = 0; i < 4; i++) {
        int row = rowbase + ty*4 + i;
        float* pp = g_partial + ((size_t)blockIdx.z*96 + row)*256;
        *(float4*)(pp + tx*4)       = make_float4(acc[i][0], acc[i][1], acc[i][2], acc[i][3]);
        *(float4*)(pp + 128 + tx*4) = make_float4(acc[i][4], acc[i][5], acc[i][6], acc[i][7]);
    }
}

// ---------------- kernel E: reduce + relu + 256x256 GEMM + relu ------------
__global__ void __launch_bounds__(256) kE(const float* __restrict__ rb0,
                                          const float* __restrict__ rw1,
                                          const float* __restrict__ rb1,
                                          float* __restrict__ out) {
    __shared__ float h2s[256];
    __shared__ float w1s[256*33];
    const int row = blockIdx.x;
    const int o = threadIdx.x;
    float s = rb0[o];
    #pragma unroll 4
    for (int ks = 0; ks < KSPLIT; ks++)
        s += g_partial[((size_t)ks*96 + row)*256 + o];
    h2s[o] = fmaxf(s, 0.f);
    __syncthreads();

    float acc = rb1[o];
    for (int jt = 0; jt < 256; jt += 32) {
        for (int i = threadIdx.x; i < 8192; i += 256) {
            int oo = i >> 5, jj = i & 31;
            w1s[oo*33 + jj] = rw1[(size_t)oo*256 + jt + jj];
        }
        __syncthreads();
        #pragma unroll
        for (int jj = 0; jj < 32; jj++)
            acc = fmaf(h2s[jt + jj], w1s[o*33 + jj], acc);
        __syncthreads();
    }
    out[(size_t)row*256 + o] = fmaxf(acc, 0.f);
}

// ---------------- launch ----------------
extern "C" void kernel_launch(void* const* d_in, const int* in_sizes, int n_in,
                              void* d_out, int out_size) {
    const float* proposals = (const float*)d_in[0];
    const float* kxyz      = (const float*)d_in[1];
    const float* kfeat     = (const float*)d_in[2];
    const float* gnoise    = (const float*)d_in[3];
    const float* w00 = (const float*)d_in[4];
    const float* b00 = (const float*)d_in[5];
    const float* w01 = (const float*)d_in[6];
    const float* b01 = (const float*)d_in[7];
    const float* w10 = (const float*)d_in[8];
    const float* b10 = (const float*)d_in[9];
    const float* w11 = (const float*)d_in[10];
    const float* b11 = (const float*)d_in[11];
    const float* rw0 = (const float*)d_in[12];
    const float* rb0 = (const float*)d_in[13];
    const float* rw1 = (const float*)d_in[14];
    const float* rb1 = (const float*)d_in[15];
    float* out = (float*)d_out;

    cudaFuncSetAttribute(kC2, cudaFuncAttributeMaxDynamicSharedMemorySize,
                         KC2_SMEM_WORDS * 4);

    kA<<<(NTOT + 255)/256, 256>>>(proposals, gnoise);
    kB<<<dim3(KKEY/32, 4), 256>>>(kfeat, w00, w10);
    kQ<<<NTOT/8, 256>>>(kxyz);
    kC2<<<NTOT/12, 384, KC2_SMEM_WORDS * 4>>>(w00, b00, w01, b01,
                                              w10, b10, w11, b11);
    kD<<<dim3(1, 96/32, KSPLIT), 256>>>(rw0);
    kE<<<96, 256>>>(rb0, rw1, rb1, out);
}

// round 10
// speedup vs baseline: 1.7249x; 1.1227x over previous
#include <cuda_runtime.h>
#include <math.h>

#define KKEY   2048
#define CFEAT  128
#define M_GRID 216
#define NPROP  48
#define NPTS   (NPROP*M_GRID)      // 10368 per batch
#define NTOT   (2*NPTS)            // 20736
#define QDIM   (128*M_GRID)        // 27648
#define KSPLIT 108
#define KCHUNK 256

typedef unsigned long long ull;

__device__ __forceinline__ ull pack2(float lo, float hi) {
    ull r; asm("mov.b64 %0, {%1, %2};" : "=l"(r) : "f"(lo), "f"(hi)); return r;
}
__device__ __forceinline__ ull ffma2(ull a, ull b, ull c) {
    ull d; asm("fma.rn.f32x2 %0, %1, %2, %3;" : "=l"(d) : "l"(a), "l"(b), "l"(c)); return d;
}
__device__ __forceinline__ float2 unpack2(ull v) {
    float2 f; asm("mov.b64 {%0, %1}, %2;" : "=f"(f.x), "=f"(f.y) : "l"(v)); return f;
}
__device__ __forceinline__ unsigned f2tf32(float v) {
    unsigned u; asm("cvt.rna.tf32.f32 %0, %1;" : "=r"(u) : "f"(v)); return u;
}
__device__ __forceinline__ void mma_tf32(float d[4], const unsigned a0, const unsigned a1,
                                         const unsigned a2, const unsigned a3,
                                         const unsigned b0, const unsigned b1) {
    asm("mma.sync.aligned.m16n8k8.row.col.f32.tf32.tf32.f32 "
        "{%0,%1,%2,%3}, {%4,%5,%6,%7}, {%8,%9}, {%0,%1,%2,%3};"
        : "+f"(d[0]), "+f"(d[1]), "+f"(d[2]), "+f"(d[3])
        : "r"(a0), "r"(a1), "r"(a2), "r"(a3), "r"(b0), "r"(b1));
}

// ---------------- scratch ----------------
__device__ float  g_new_xyz[NTOT*3];
__device__ float  g_pre[2*2*KKEY*64];        // [scale][b][k][interleaved o]
__device__ float4 g_rel1[NTOT*32];           // {rx,ry,rz, bitcast k}
__device__ float4 g_rel0[NTOT*16];
__device__ float  g_pooled[2*NPROP*QDIM];    // 96 x 27648, q = co*216+mm
__device__ float  g_partial[KSPLIT*96*256];

// ---------------- kernel A ----------------
__global__ void __launch_bounds__(256) kA(const float* __restrict__ prop,
                                          const float* __restrict__ gnoise) {
    int t = blockIdx.x*256 + threadIdx.x;
    if (t >= NTOT) return;
    int b = t / NPTS, r = t % NPTS;
    int n = r / M_GRID, mm = r % M_GRID;
    const float* p = prop + (size_t)(b*NPROP + n)*7;
    const float* g = gnoise + ((size_t)(b*NPROP + n)*M_GRID + mm)*3;
    float gx = g[0]*p[3], gy = g[1]*p[4], gz = g[2]*p[5];
    float c = cosf(p[6]), s = sinf(p[6]);
    float* o = g_new_xyz + (size_t)t*3;
    o[0] = c*gx - s*gy + p[0];
    o[1] = s*gx + c*gy + p[1];
    o[2] = gz + p[2];
}

// ---------------- kernel B: pre[k][o] = W0[:,3:] . feats[:,k] ----------------
__global__ void __launch_bounds__(256) kB(const float* __restrict__ feats,
                                          const float* __restrict__ w0,
                                          const float* __restrict__ w1) {
    __shared__ float Ws[CFEAT*64];
    __shared__ float fs[CFEAT*32];
    int sb = blockIdx.y; int sc = sb >> 1, b = sb & 1;
    const float* W = sc ? w1 : w0;
    for (int i = threadIdx.x; i < CFEAT*64; i += 256) {
        int c = i >> 6, o = i & 63;
        Ws[i] = W[o*131 + 3 + c];
    }
    int kbase = blockIdx.x * 32;
    const float* fb = feats + (size_t)b*CFEAT*KKEY + kbase;
    for (int i = threadIdx.x; i < CFEAT*8; i += 256) {
        int c = i >> 3, q = i & 7;
        *(float4*)(fs + c*32 + q*4) = *(const float4*)(fb + (size_t)c*KKEY + q*4);
    }
    __syncthreads();

    int o  = threadIdx.x & 63;
    int kk = threadIdx.x >> 6;
    ull acc0 = 0, acc1 = 0, acc2 = 0, acc3 = 0;
    #pragma unroll 4
    for (int c = 0; c < CFEAT; c++) {
        float w = Ws[c*64 + o];
        ull wd = pack2(w, w);
        const ull* f = (const ull*)(fs + c*32 + kk*8);
        acc0 = ffma2(wd, f[0], acc0);
        acc1 = ffma2(wd, f[1], acc1);
        acc2 = ffma2(wd, f[2], acc2);
        acc3 = ffma2(wd, f[3], acc3);
    }
    size_t base = ((size_t)(sc*2 + b)*KKEY + kbase + kk*8) << 6;
    int oi = ((o & 31) << 1) + (o >> 5);
    float2 u;
    u = unpack2(acc0); g_pre[base + oi] = u.x; g_pre[base + 64 + oi] = u.y;
    u = unpack2(acc1); g_pre[base + 128 + oi] = u.x; g_pre[base + 192 + oi] = u.y;
    u = unpack2(acc2); g_pre[base + 256 + oi] = u.x; g_pre[base + 320 + oi] = u.y;
    u = unpack2(acc3); g_pre[base + 384 + oi] = u.x; g_pre[base + 448 + oi] = u.y;
}

// ---------------- kernel Q: ball query -> padded idx + rel coords ----------
// 512 threads = 16 points/block (halves keypoint smem-fill per point)
__global__ void __launch_bounds__(512) kQ(const float* __restrict__ kxyzg) {
    __shared__ float kp[KKEY*3];               // interleaved xyz
    __shared__ int idx1s[16][32], idx0s[16][16];

    const int b = blockIdx.x / 648;
    const float* kb = kxyzg + (size_t)b*KKEY*3;
    for (int i = threadIdx.x; i < KKEY*3; i += 512) kp[i] = kb[i];
    __syncthreads();

    const int w = threadIdx.x >> 5, lane = threadIdx.x & 31;
    const int p = blockIdx.x*16 + w;
    const float px = g_new_xyz[(size_t)p*3], py = g_new_xyz[(size_t)p*3+1],
                pz = g_new_xyz[(size_t)p*3+2];
    const float pn = fmaf(px,px, fmaf(py,py, pz*pz));

    const float R0 = 0.8f*0.8f, R1 = 1.6f*1.6f;
    int* l1 = idx1s[w];
    int* l0 = idx0s[w];
    int c0 = 0, c1 = 0;
    const unsigned lt = (1u << lane) - 1u;
    for (int base = 0; base < KKEY; base += 32) {
        int k = base + lane;
        float kx = kp[3*k], ky = kp[3*k+1], kz = kp[3*k+2];
        float kn  = fmaf(kx,kx, fmaf(ky,ky, kz*kz));
        float dot = fmaf(px,kx, fmaf(py,ky, pz*kz));
        float d2  = fmaf(-2.f, dot, pn + kn);
        bool v1 = d2 < R1, v0 = d2 < R0;
        unsigned m1 = __ballot_sync(0xffffffffu, v1);
        unsigned m0 = __ballot_sync(0xffffffffu, v0);
        if (c1 < 32 && m1) {
            if (v1) { int rk = c1 + __popc(m1 & lt); if (rk < 32) l1[rk] = k; }
            c1 = min(32, c1 + __popc(m1));
        }
        if (c0 < 16 && m0) {
            if (v0) { int rk = c0 + __popc(m0 & lt); if (rk < 16) l0[rk] = k; }
            c0 = min(16, c0 + __popc(m0));
        }
        if (c0 >= 16 && c1 >= 32) break;
    }
    __syncwarp();
    if (c1 == 0) { if (lane == 0) l1[0] = 0; c1 = 1; }
    if (c0 == 0) { if (lane == 0) l0[0] = 0; c0 = 1; }
    __syncwarp();
    {
        int f1 = l1[0], f0 = l0[0];
        if (lane >= c1) l1[lane] = f1;
        if (lane < 16 && lane >= c0) l0[lane] = f0;
    }
    __syncwarp();

    {
        int k = l1[lane];
        g_rel1[(size_t)p*32 + lane] =
            make_float4(kp[3*k]-px, kp[3*k+1]-py, kp[3*k+2]-pz, __int_as_float(k));
        if (lane < 16) {
            int k0 = l0[lane];
            g_rel0[(size_t)p*16 + lane] =
                make_float4(kp[3*k0]-px, kp[3*k0+1]-py, kp[3*k0+2]-pz, __int_as_float(k0));
        }
    }
}

// ---------------- kernel C2: 1 pt/warp, smem-staged rel + packed frags ------
// (unchanged from R9 — validated at 105.6us)
#define KC2_SMEM_WORDS 24960
#define OFF2_WXYZ 8192
#define OFF2_B0   8576
#define OFF2_B1   8704
#define OFF2_HW   8832
#define OFF2_REL  22656
#define HW_PITCH  72

__global__ void __launch_bounds__(384, 2) kC2(
    const float* __restrict__ w00, const float* __restrict__ b00,
    const float* __restrict__ w01, const float* __restrict__ b01,
    const float* __restrict__ w10, const float* __restrict__ b10,
    const float* __restrict__ w11, const float* __restrict__ b11)
{
    extern __shared__ float sm[];
    uint2*    wpk  = (uint2*)sm;               // [sc][kt][nt][lane]
    float*    wxyz = sm + OFF2_WXYZ;
    float*    b0s  = sm + OFF2_B0;
    float*    b1s  = sm + OFF2_B1;
    unsigned* hwg  = (unsigned*)(sm + OFF2_HW);
    float4*   relg = (float4*)(sm + OFF2_REL); // [12 warps][48]

    for (int i = threadIdx.x; i < 2*8*8*32; i += 384) {
        int lane2 = i & 31, nt = (i >> 5) & 7, kt = (i >> 8) & 7, sc = i >> 11;
        int gid2 = lane2 >> 2, tig2 = lane2 & 3;
        const float* W1 = sc ? w11 : w01;
        int o = nt*8 + gid2;
        int j = kt*4 + tig2;
        wpk[i] = make_uint2(f2tf32(W1[o*64 + j]), f2tf32(W1[o*64 + j + 32]));
    }
    for (int i = threadIdx.x; i < 2*3*64; i += 384) {
        int sc = i / 192, t = i % 192, d = t / 64, o = t % 64;
        wxyz[i] = (sc ? w10 : w00)[o*131 + d];
    }
    if (threadIdx.x < 256) {
        int sc = (threadIdx.x >> 6) & 1, o = threadIdx.x & 63;
        if (threadIdx.x < 128) b0s[threadIdx.x] = (sc ? b10 : b00)[o];
        else                   b1s[threadIdx.x - 128] = (sc ? b11 : b01)[o];
    }
    __syncthreads();

    const int w = threadIdx.x >> 5, lane = threadIdx.x & 31;
    const int gid = lane >> 2, tig = lane & 3;
    const int p  = blockIdx.x*12 + w;
    const int b  = p / NPTS;
    const int rp = p % NPTS;
    const int n  = rp / M_GRID, mm = rp % M_GRID;

    unsigned* hw = hwg + w*16*HW_PITCH;
    float4*   relw = relg + w*48;
    const int sts_off = (lane >> 2)*8 + (lane & 3)*2;

    relw[16 + lane] = g_rel1[(size_t)p*32 + lane];
    if (lane < 16) relw[lane] = g_rel0[(size_t)p*16 + lane];
    __syncwarp();

    #pragma unroll
    for (int sc = 0; sc < 2; sc++) {
        const int NPASS = sc ? 2 : 1;
        const float* preb = g_pre + ((size_t)(sc*2 + b)*KKEY << 6);
        const uint2* wps = wpk + sc*2048;
        const float* wx = wxyz + sc*192;
        const float bias0a = b0s[sc*64 + lane],  bias0b = b0s[sc*64 + lane + 32];
        const float wxa0 = wx[lane],    wxa1 = wx[64+lane],  wxa2 = wx[128+lane];
        const float wxb0 = wx[lane+32], wxb1 = wx[96+lane],  wxb2 = wx[160+lane];

        float cm0[8], cm1[8];
        #pragma unroll
        for (int nt = 0; nt < 8; nt++) { cm0[nt] = -3.4e38f; cm1[nt] = -3.4e38f; }

        for (int pass = 0; pass < NPASS; pass++) {
            const float4* relb = sc ? (relw + 16 + pass*16) : relw;
            #pragma unroll
            for (int s0 = 0; s0 < 16; s0 += 4) {
                float4 rv[4];
                float2 pr[4];
                #pragma unroll
                for (int s = 0; s < 4; s++) {
                    rv[s] = relb[s0 + s];
                    int k = __float_as_int(rv[s].w);
                    pr[s] = *(const float2*)(preb + ((size_t)k << 6) + (lane << 1));
                }
                #pragma unroll
                for (int s = 0; s < 4; s++) {
                    float va = pr[s].x + bias0a;
                    va = fmaf(rv[s].x, wxa0, va);
                    va = fmaf(rv[s].y, wxa1, va);
                    va = fmaf(rv[s].z, wxa2, va);
                    float vb = pr[s].y + bias0b;
                    vb = fmaf(rv[s].x, wxb0, vb);
                    vb = fmaf(rv[s].y, wxb1, vb);
                    vb = fmaf(rv[s].z, wxb2, vb);
                    *(uint2*)(hw + (s0+s)*HW_PITCH + sts_off) =
                        make_uint2(f2tf32(fmaxf(va, 0.f)), f2tf32(fmaxf(vb, 0.f)));
                }
            }
            __syncwarp();

            float acc[8][4];
            #pragma unroll
            for (int nt = 0; nt < 8; nt++)
                acc[nt][0] = acc[nt][1] = acc[nt][2] = acc[nt][3] = 0.f;
            #pragma unroll
            for (int kt = 0; kt < 8; kt++) {
                uint2 alo = *(const uint2*)(hw + gid*HW_PITCH + kt*8 + tig*2);
                uint2 ahi = *(const uint2*)(hw + (gid+8)*HW_PITCH + kt*8 + tig*2);
                const uint2* wrow = wps + kt*256 + lane;
                #pragma unroll
                for (int nt = 0; nt < 8; nt++) {
                    uint2 bb = wrow[nt*32];
                    mma_tf32(acc[nt], alo.x, ahi.x, alo.y, ahi.y, bb.x, bb.y);
                }
            }
            #pragma unroll
            for (int nt = 0; nt < 8; nt++) {
                cm0[nt] = fmaxf(cm0[nt], fmaxf(acc[nt][0], acc[nt][2]));
                cm1[nt] = fmaxf(cm1[nt], fmaxf(acc[nt][1], acc[nt][3]));
            }
            __syncwarp();
        }

        #pragma unroll
        for (int off = 4; off <= 16; off <<= 1) {
            #pragma unroll
            for (int nt = 0; nt < 8; nt++) {
                cm0[nt] = fmaxf(cm0[nt], __shfl_xor_sync(0xffffffffu, cm0[nt], off));
                cm1[nt] = fmaxf(cm1[nt], __shfl_xor_sync(0xffffffffu, cm1[nt], off));
            }
        }
        size_t rowb = (size_t)(b*NPROP + n)*QDIM + (size_t)sc*64*M_GRID + mm;
        if (gid == 0) {
            #pragma unroll
            for (int nt = 0; nt < 8; nt++) {
                int o0 = nt*8 + tig*2;
                float v0 = fmaxf(cm0[nt] + b1s[sc*64 + o0],     0.f);
                float v1 = fmaxf(cm1[nt] + b1s[sc*64 + o0 + 1], 0.f);
                g_pooled[rowb + (size_t)o0*M_GRID]     = v0;
                g_pooled[rowb + (size_t)(o0+1)*M_GRID] = v1;
            }
        }
    }
}

// ---------------- kernel D: K-split GEMM via tf32 MMA ----------------------
// 384 thr = 12 warps: 6 rowgroups (16 rows) x 2 colgroups (32 cols = 4 nt).
// Block tile 96 x 64; grid (4 colblocks, KSPLIT). k-tile 16 (2 mma-k steps).
// Permuted k slot within 16: slot(kk) = ((kk&7)>>2)*8 + (kk&3)*2 + (kk>>3),
// same fragment convention as kC2 (validated): a=(alo.x,ahi.x,alo.y,ahi.y).
#define XDP 18
__global__ void __launch_bounds__(384) kD(const float* __restrict__ w0) {
    __shared__ unsigned xs[2][96*XDP];
    __shared__ unsigned ws[2][64*XDP];
    const int tid = threadIdx.x;
    const int w = tid >> 5, lane = tid & 31;
    const int gid = lane >> 2, tig = lane & 3;
    const int rg = w % 6, cg = w / 6;
    const int colbase = blockIdx.x * 64;
    const int kg0 = blockIdx.y * KCHUNK;

    const int frow = tid >> 2;                 // 0..95
    const int fq   = (tid & 3) << 2;           // 0,4,8,12
    const int slotb = ((fq & 4) << 1) + (fq >> 3);   // quad slot base

    const float* xg = g_pooled + (size_t)frow*QDIM + kg0 + fq;
    const float* wg = w0 + (size_t)(colbase + (tid >> 2))*QDIM + kg0 + ((tid & 3) << 2);

    float4 xv = *(const float4*)xg;
    float4 wv = make_float4(0.f,0.f,0.f,0.f);
    if (tid < 256) wv = *(const float4*)wg;

    float acc[4][4] = {};
    const int NT = KCHUNK / 16;                 // 16
    for (int t = 0; t < NT; t++) {
        unsigned* xsc = xs[t & 1];
        unsigned* wsc = ws[t & 1];
        {
            unsigned* d = xsc + frow*XDP + slotb;
            d[0] = f2tf32(xv.x); d[2] = f2tf32(xv.y);
            d[4] = f2tf32(xv.z); d[6] = f2tf32(xv.w);
        }
        if (tid < 256) {
            unsigned* d = wsc + (tid >> 2)*XDP + slotb;
            d[0] = f2tf32(wv.x); d[2] = f2tf32(wv.y);
            d[4] = f2tf32(wv.z); d[6] = f2tf32(wv.w);
        }
        __syncthreads();
        if (t + 1 < NT) {
            xv = *(const float4*)(xg + (t + 1)*16);
            if (tid < 256) wv = *(const float4*)(wg + (t + 1)*16);
        }
        #pragma unroll
        for (int kt = 0; kt < 2; kt++) {
            uint2 alo = *(const uint2*)(xsc + (rg*16 + gid    )*XDP + kt*8 + tig*2);
            uint2 ahi = *(const uint2*)(xsc + (rg*16 + gid + 8)*XDP + kt*8 + tig*2);
            #pragma unroll
            for (int nt = 0; nt < 4; nt++) {
                uint2 bb = *(const uint2*)(wsc + (cg*32 + nt*8 + gid)*XDP + kt*8 + tig*2);
                mma_tf32(acc[nt], alo.x, ahi.x, alo.y, ahi.y, bb.x, bb.y);
            }
        }
        __syncthreads();
    }
    #pragma unroll
    for (int nt = 0; nt < 4; nt++) {
        int col = colbase + cg*32 + nt*8 + tig*2;
        int row = rg*16 + gid;
        float* pp = g_partial + ((size_t)blockIdx.y*96 + row)*256 + col;
        *(float2*)pp             = make_float2(acc[nt][0], acc[nt][1]);
        *(float2*)(pp + 8*256)   = make_float2(acc[nt][2], acc[nt][3]);
    }
}

// ---------------- kernel E: reduce + relu + 256x256 GEMM + relu ------------
__global__ void __launch_bounds__(256) kE(const float* __restrict__ rb0,
                                          const float* __restrict__ rw1,
                                          const float* __restrict__ rb1,
                                          float* __restrict__ out) {
    __shared__ float h2s[256];
    __shared__ float w1s[256*33];
    const int row = blockIdx.x;
    const int o = threadIdx.x;
    float s = rb0[o];
    #pragma unroll 4
    for (int ks = 0; ks < KSPLIT; ks++)
        s += g_partial[((size_t)ks*96 + row)*256 + o];
    h2s[o] = fmaxf(s, 0.f);
    __syncthreads();

    float acc = rb1[o];
    for (int jt = 0; jt < 256; jt += 32) {
        for (int i = threadIdx.x; i < 8192; i += 256) {
            int oo = i >> 5, jj = i & 31;
            w1s[oo*33 + jj] = rw1[(size_t)oo*256 + jt + jj];
        }
        __syncthreads();
        #pragma unroll
        for (int jj = 0; jj < 32; jj++)
            acc = fmaf(h2s[jt + jj], w1s[o*33 + jj], acc);
        __syncthreads();
    }
    out[(size_t)row*256 + o] = fmaxf(acc, 0.f);
}

// ---------------- launch ----------------
extern "C" void kernel_launch(void* const* d_in, const int* in_sizes, int n_in,
                              void* d_out, int out_size) {
    const float* proposals = (const float*)d_in[0];
    const float* kxyz      = (const float*)d_in[1];
    const float* kfeat     = (const float*)d_in[2];
    const float* gnoise    = (const float*)d_in[3];
    const float* w00 = (const float*)d_in[4];
    const float* b00 = (const float*)d_in[5];
    const float* w01 = (const float*)d_in[6];
    const float* b01 = (const float*)d_in[7];
    const float* w10 = (const float*)d_in[8];
    const float* b10 = (const float*)d_in[9];
    const float* w11 = (const float*)d_in[10];
    const float* b11 = (const float*)d_in[11];
    const float* rw0 = (const float*)d_in[12];
    const float* rb0 = (const float*)d_in[13];
    const float* rw1 = (const float*)d_in[14];
    const float* rb1 = (const float*)d_in[15];
    float* out = (float*)d_out;

    cudaFuncSetAttribute(kC2, cudaFuncAttributeMaxDynamicSharedMemorySize,
                         KC2_SMEM_WORDS * 4);

    kA<<<(NTOT + 255)/256, 256>>>(proposals, gnoise);
    kB<<<dim3(KKEY/32, 4), 256>>>(kfeat, w00, w10);
    kQ<<<NTOT/16, 512>>>(kxyz);
    kC2<<<NTOT/12, 384, KC2_SMEM_WORDS * 4>>>(w00, b00, w01, b01,
                                              w10, b10, w11, b11);
    kD<<<dim3(4, KSPLIT), 384>>>(rw0);
    kE<<<96, 256>>>(rb0, rw1, rb1, out);
}

// round 11
// speedup vs baseline: 1.7384x; 1.0078x over previous
#include <cuda_runtime.h>
#include <math.h>

#define KKEY   2048
#define CFEAT  128
#define M_GRID 216
#define NPROP  48
#define NPTS   (NPROP*M_GRID)      // 10368 per batch
#define NTOT   (2*NPTS)            // 20736
#define QDIM   (128*M_GRID)        // 27648
#define KSPLIT 108
#define KCHUNK 256

typedef unsigned long long ull;

__device__ __forceinline__ ull pack2(float lo, float hi) {
    ull r; asm("mov.b64 %0, {%1, %2};" : "=l"(r) : "f"(lo), "f"(hi)); return r;
}
__device__ __forceinline__ ull ffma2(ull a, ull b, ull c) {
    ull d; asm("fma.rn.f32x2 %0, %1, %2, %3;" : "=l"(d) : "l"(a), "l"(b), "l"(c)); return d;
}
__device__ __forceinline__ float2 unpack2(ull v) {
    float2 f; asm("mov.b64 {%0, %1}, %2;" : "=f"(f.x), "=f"(f.y) : "l"(v)); return f;
}
__device__ __forceinline__ unsigned f2tf32(float v) {
    unsigned u; asm("cvt.rna.tf32.f32 %0, %1;" : "=r"(u) : "f"(v)); return u;
}
__device__ __forceinline__ void mma_tf32(float d[4], const unsigned a0, const unsigned a1,
                                         const unsigned a2, const unsigned a3,
                                         const unsigned b0, const unsigned b1) {
    asm("mma.sync.aligned.m16n8k8.row.col.f32.tf32.tf32.f32 "
        "{%0,%1,%2,%3}, {%4,%5,%6,%7}, {%8,%9}, {%0,%1,%2,%3};"
        : "+f"(d[0]), "+f"(d[1]), "+f"(d[2]), "+f"(d[3])
        : "r"(a0), "r"(a1), "r"(a2), "r"(a3), "r"(b0), "r"(b1));
}

// ---------------- scratch ----------------
__device__ float  g_new_xyz[NTOT*3];
__device__ float  g_pre[2*2*KKEY*64];        // [scale][b][k][interleaved o]
__device__ float4 g_rel1[NTOT*32];           // {rx,ry,rz, bitcast k}
__device__ float4 g_rel0[NTOT*16];
__device__ float  g_pooled[2*NPROP*QDIM];    // 96 x 27648, q = co*216+mm
__device__ float  g_partial[KSPLIT*96*256];

// ---------------- kernel A ----------------
__global__ void __launch_bounds__(256) kA(const float* __restrict__ prop,
                                          const float* __restrict__ gnoise) {
    int t = blockIdx.x*256 + threadIdx.x;
    if (t >= NTOT) return;
    int b = t / NPTS, r = t % NPTS;
    int n = r / M_GRID, mm = r % M_GRID;
    const float* p = prop + (size_t)(b*NPROP + n)*7;
    const float* g = gnoise + ((size_t)(b*NPROP + n)*M_GRID + mm)*3;
    float gx = g[0]*p[3], gy = g[1]*p[4], gz = g[2]*p[5];
    float c = cosf(p[6]), s = sinf(p[6]);
    float* o = g_new_xyz + (size_t)t*3;
    o[0] = c*gx - s*gy + p[0];
    o[1] = s*gx + c*gy + p[1];
    o[2] = gz + p[2];
}

// ---------------- kernel B: pre[k][o] = W0[:,3:] . feats[:,k] ----------------
__global__ void __launch_bounds__(256) kB(const float* __restrict__ feats,
                                          const float* __restrict__ w0,
                                          const float* __restrict__ w1) {
    __shared__ float Ws[CFEAT*64];
    __shared__ float fs[CFEAT*32];
    int sb = blockIdx.y; int sc = sb >> 1, b = sb & 1;
    const float* W = sc ? w1 : w0;
    for (int i = threadIdx.x; i < CFEAT*64; i += 256) {
        int c = i >> 6, o = i & 63;
        Ws[i] = W[o*131 + 3 + c];
    }
    int kbase = blockIdx.x * 32;
    const float* fb = feats + (size_t)b*CFEAT*KKEY + kbase;
    for (int i = threadIdx.x; i < CFEAT*8; i += 256) {
        int c = i >> 3, q = i & 7;
        *(float4*)(fs + c*32 + q*4) = *(const float4*)(fb + (size_t)c*KKEY + q*4);
    }
    __syncthreads();

    int o  = threadIdx.x & 63;
    int kk = threadIdx.x >> 6;
    ull acc0 = 0, acc1 = 0, acc2 = 0, acc3 = 0;
    #pragma unroll 4
    for (int c = 0; c < CFEAT; c++) {
        float w = Ws[c*64 + o];
        ull wd = pack2(w, w);
        const ull* f = (const ull*)(fs + c*32 + kk*8);
        acc0 = ffma2(wd, f[0], acc0);
        acc1 = ffma2(wd, f[1], acc1);
        acc2 = ffma2(wd, f[2], acc2);
        acc3 = ffma2(wd, f[3], acc3);
    }
    size_t base = ((size_t)(sc*2 + b)*KKEY + kbase + kk*8) << 6;
    int oi = ((o & 31) << 1) + (o >> 5);
    float2 u;
    u = unpack2(acc0); g_pre[base + oi] = u.x; g_pre[base + 64 + oi] = u.y;
    u = unpack2(acc1); g_pre[base + 128 + oi] = u.x; g_pre[base + 192 + oi] = u.y;
    u = unpack2(acc2); g_pre[base + 256 + oi] = u.x; g_pre[base + 320 + oi] = u.y;
    u = unpack2(acc3); g_pre[base + 384 + oi] = u.x; g_pre[base + 448 + oi] = u.y;
}

// ---------------- kernel Q: ball query -> padded idx + rel coords ----------
// 512 threads = 16 points/block; keypoints staged as float4 {x,y,z,|k|^2}
__global__ void __launch_bounds__(512) kQ(const float* __restrict__ kxyzg) {
    __shared__ float4 kp4[KKEY];               // 32KB
    __shared__ int idx1s[16][32], idx0s[16][16];

    const int b = blockIdx.x / 648;
    const float* kb = kxyzg + (size_t)b*KKEY*3;
    for (int i = threadIdx.x; i < KKEY; i += 512) {
        float x = kb[i*3], y = kb[i*3+1], z = kb[i*3+2];
        kp4[i] = make_float4(x, y, z, fmaf(x,x, fmaf(y,y, z*z)));
    }
    __syncthreads();

    const int w = threadIdx.x >> 5, lane = threadIdx.x & 31;
    const int p = blockIdx.x*16 + w;
    const float px = g_new_xyz[(size_t)p*3], py = g_new_xyz[(size_t)p*3+1],
                pz = g_new_xyz[(size_t)p*3+2];
    const float pn = fmaf(px,px, fmaf(py,py, pz*pz));

    const float R0 = 0.8f*0.8f, R1 = 1.6f*1.6f;
    int* l1 = idx1s[w];
    int* l0 = idx0s[w];
    int c0 = 0, c1 = 0;
    const unsigned lt = (1u << lane) - 1u;
    for (int base = 0; base < KKEY; base += 32) {
        int k = base + lane;
        float4 kk = kp4[k];
        float dot = fmaf(px,kk.x, fmaf(py,kk.y, pz*kk.z));
        float d2  = fmaf(-2.f, dot, pn + kk.w);
        bool v1 = d2 < R1, v0 = d2 < R0;
        unsigned m1 = __ballot_sync(0xffffffffu, v1);
        unsigned m0 = __ballot_sync(0xffffffffu, v0);
        if (c1 < 32 && m1) {
            if (v1) { int rk = c1 + __popc(m1 & lt); if (rk < 32) l1[rk] = k; }
            c1 = min(32, c1 + __popc(m1));
        }
        if (c0 < 16 && m0) {
            if (v0) { int rk = c0 + __popc(m0 & lt); if (rk < 16) l0[rk] = k; }
            c0 = min(16, c0 + __popc(m0));
        }
        if (c0 >= 16 && c1 >= 32) break;
    }
    __syncwarp();
    if (c1 == 0) { if (lane == 0) l1[0] = 0; c1 = 1; }
    if (c0 == 0) { if (lane == 0) l0[0] = 0; c0 = 1; }
    __syncwarp();
    {
        int f1 = l1[0], f0 = l0[0];
        if (lane >= c1) l1[lane] = f1;
        if (lane < 16 && lane >= c0) l0[lane] = f0;
    }
    __syncwarp();

    {
        int k = l1[lane];
        float4 kk = kp4[k];
        g_rel1[(size_t)p*32 + lane] =
            make_float4(kk.x-px, kk.y-py, kk.z-pz, __int_as_float(k));
        if (lane < 16) {
            int k0 = l0[lane];
            float4 k4 = kp4[k0];
            g_rel0[(size_t)p*16 + lane] =
                make_float4(k4.x-px, k4.y-py, k4.z-pz, __int_as_float(k0));
        }
    }
}

// ---------------- kernel C2: 1 pt/warp, all-128-bit smem traffic ------------
// 384 threads = 12 warps = 12 points/block.
// hw row-pair layout: row r (0..7) holds samples (r, r+8) interleaved:
//   uint4 {va(r), va(r+8), vb(r), vb(r+8)} at [r*144 + gid*16 + tig*4] (u32).
//   Row pitch 144 u32 = 576B (== 64 mod 128 -> a-frag LDS.128 conflict-free).
// a-fragment = ONE LDS.128: af = {a0,a1,a2,a3} (same values as R10's alo/ahi).
// b-table layout [sc][kt][lane][nt pad10] uint2: nt contiguous -> one LDS.128
//   covers 2 nt. Lane pitch 10 uint2 = 80B (stride 20 words mod 32 -> CF).
// dyn smem words:
//  wpk  0     .. 10240   (2*8*32*10 uint2)
//  wxyz 10240 .. 10624
//  b0s  10624 .. 10752
//  b1s  10752 .. 10880
//  hw   10880 .. 24704   (12 warps * 8 rows * 144)
//  rel  24704 .. 27008   (12 warps * 48 float4)
#define KC2_SMEM_WORDS 27008
#define OFF2_WXYZ 10240
#define OFF2_B0   10624
#define OFF2_B1   10752
#define OFF2_HW   10880
#define OFF2_REL  24704
#define HW_PITCH  144

__global__ void __launch_bounds__(384, 2) kC2(
    const float* __restrict__ w00, const float* __restrict__ b00,
    const float* __restrict__ w01, const float* __restrict__ b01,
    const float* __restrict__ w10, const float* __restrict__ b10,
    const float* __restrict__ w11, const float* __restrict__ b11)
{
    extern __shared__ float sm[];
    uint2*    wpk  = (uint2*)sm;               // [sc][kt][lane][nt pad10]
    float*    wxyz = sm + OFF2_WXYZ;
    float*    b0s  = sm + OFF2_B0;
    float*    b1s  = sm + OFF2_B1;
    unsigned* hwg  = (unsigned*)(sm + OFF2_HW);
    float4*   relg = (float4*)(sm + OFF2_REL);

    // b-table: same VALUES as R10 (validated), new layout
    for (int i = threadIdx.x; i < 2*8*32*8; i += 384) {
        int nt = i & 7, lane2 = (i >> 3) & 31, kt = (i >> 8) & 7, sc = i >> 11;
        int gid2 = lane2 >> 2, tig2 = lane2 & 3;
        const float* W1 = sc ? w11 : w01;
        int o = nt*8 + gid2;
        int j = kt*4 + tig2;
        wpk[sc*2560 + kt*320 + lane2*10 + nt] =
            make_uint2(f2tf32(W1[o*64 + j]), f2tf32(W1[o*64 + j + 32]));
    }
    for (int i = threadIdx.x; i < 2*3*64; i += 384) {
        int sc = i / 192, t = i % 192, d = t / 64, o = t % 64;
        wxyz[i] = (sc ? w10 : w00)[o*131 + d];
    }
    if (threadIdx.x < 256) {
        int sc = (threadIdx.x >> 6) & 1, o = threadIdx.x & 63;
        if (threadIdx.x < 128) b0s[threadIdx.x] = (sc ? b10 : b00)[o];
        else                   b1s[threadIdx.x - 128] = (sc ? b11 : b01)[o];
    }
    __syncthreads();

    const int w = threadIdx.x >> 5, lane = threadIdx.x & 31;
    const int gid = lane >> 2, tig = lane & 3;
    const int p  = blockIdx.x*12 + w;
    const int b  = p / NPTS;
    const int rp = p % NPTS;
    const int n  = rp / M_GRID, mm = rp % M_GRID;

    unsigned* hw = hwg + w*8*HW_PITCH;
    float4*   relw = relg + w*48;
    const int colu = gid*16 + tig*4;           // u32 column within a row

    relw[16 + lane] = g_rel1[(size_t)p*32 + lane];
    if (lane < 16) relw[lane] = g_rel0[(size_t)p*16 + lane];
    __syncwarp();

    #pragma unroll
    for (int sc = 0; sc < 2; sc++) {
        const int NPASS = sc ? 2 : 1;
        const float* preb = g_pre + ((size_t)(sc*2 + b)*KKEY << 6);
        const uint2* wps = wpk + sc*2560;
        const float* wx = wxyz + sc*192;
        const float bias0a = b0s[sc*64 + lane],  bias0b = b0s[sc*64 + lane + 32];
        const float wxa0 = wx[lane],    wxa1 = wx[64+lane],  wxa2 = wx[128+lane];
        const float wxb0 = wx[lane+32], wxb1 = wx[96+lane],  wxb2 = wx[160+lane];

        float cm0[8], cm1[8];
        #pragma unroll
        for (int nt = 0; nt < 8; nt++) { cm0[nt] = -3.4e38f; cm1[nt] = -3.4e38f; }

        for (int pass = 0; pass < NPASS; pass++) {
            const float4* relb = sc ? (relw + 16 + pass*16) : relw;
            // ---- layer 0: 16 samples, row-paired (s, s+8), STS.128 ----
            #pragma unroll
            for (int sb = 0; sb < 8; sb += 2) {
                float4 rv[4];
                float2 pr[4];
                // q order: {sb, sb+1, sb+8, sb+9}
                #pragma unroll
                for (int q = 0; q < 4; q++) {
                    int si = sb + (q & 1) + ((q >> 1) << 3);
                    rv[q] = relb[si];
                    int k = __float_as_int(rv[q].w);
                    pr[q] = *(const float2*)(preb + ((size_t)k << 6) + (lane << 1));
                }
                unsigned va[4], vb[4];
                #pragma unroll
                for (int q = 0; q < 4; q++) {
                    float a = pr[q].x + bias0a;
                    a = fmaf(rv[q].x, wxa0, a);
                    a = fmaf(rv[q].y, wxa1, a);
                    a = fmaf(rv[q].z, wxa2, a);
                    float bv = pr[q].y + bias0b;
                    bv = fmaf(rv[q].x, wxb0, bv);
                    bv = fmaf(rv[q].y, wxb1, bv);
                    bv = fmaf(rv[q].z, wxb2, bv);
                    va[q] = f2tf32(fmaxf(a, 0.f));
                    vb[q] = f2tf32(fmaxf(bv, 0.f));
                }
                *(uint4*)(hw + (sb  )*HW_PITCH + colu) =
                    make_uint4(va[0], va[2], vb[0], vb[2]);
                *(uint4*)(hw + (sb+1)*HW_PITCH + colu) =
                    make_uint4(va[1], va[3], vb[1], vb[3]);
            }
            __syncwarp();

            // ---- layer 1 MMA: a = 1 LDS.128, b = 4 LDS.128 per kt ----
            float acc[8][4];
            #pragma unroll
            for (int nt = 0; nt < 8; nt++)
                acc[nt][0] = acc[nt][1] = acc[nt][2] = acc[nt][3] = 0.f;
            #pragma unroll
            for (int kt = 0; kt < 8; kt++) {
                uint4 af = *(const uint4*)(hw + gid*HW_PITCH + kt*16 + tig*4);
                const uint2* wk = wps + kt*320 + lane*10;
                #pragma unroll
                for (int ntp = 0; ntp < 4; ntp++) {
                    uint4 bp = *(const uint4*)(wk + ntp*2);
                    mma_tf32(acc[2*ntp],   af.x, af.y, af.z, af.w, bp.x, bp.y);
                    mma_tf32(acc[2*ntp+1], af.x, af.y, af.z, af.w, bp.z, bp.w);
                }
            }
            #pragma unroll
            for (int nt = 0; nt < 8; nt++) {
                cm0[nt] = fmaxf(cm0[nt], fmaxf(acc[nt][0], acc[nt][2]));
                cm1[nt] = fmaxf(cm1[nt], fmaxf(acc[nt][1], acc[nt][3]));
            }
            __syncwarp();
        }

        // reduce across row-groups (lane bits 2..4)
        #pragma unroll
        for (int off = 4; off <= 16; off <<= 1) {
            #pragma unroll
            for (int nt = 0; nt < 8; nt++) {
                cm0[nt] = fmaxf(cm0[nt], __shfl_xor_sync(0xffffffffu, cm0[nt], off));
                cm1[nt] = fmaxf(cm1[nt], __shfl_xor_sync(0xffffffffu, cm1[nt], off));
            }
        }
        size_t rowb = (size_t)(b*NPROP + n)*QDIM + (size_t)sc*64*M_GRID + mm;
        if (gid == 0) {
            #pragma unroll
            for (int nt = 0; nt < 8; nt++) {
                int o0 = nt*8 + tig*2;
                float v0 = fmaxf(cm0[nt] + b1s[sc*64 + o0],     0.f);
                float v1 = fmaxf(cm1[nt] + b1s[sc*64 + o0 + 1], 0.f);
                g_pooled[rowb + (size_t)o0*M_GRID]     = v0;
                g_pooled[rowb + (size_t)(o0+1)*M_GRID] = v1;
            }
        }
    }
}

// ---------------- kernel D: K-split GEMM via tf32 MMA (R10, validated) ------
#define XDP 18
__global__ void __launch_bounds__(384) kD(const float* __restrict__ w0) {
    __shared__ unsigned xs[2][96*XDP];
    __shared__ unsigned ws[2][64*XDP];
    const int tid = threadIdx.x;
    const int w = tid >> 5, lane = tid & 31;
    const int gid = lane >> 2, tig = lane & 3;
    const int rg = w % 6, cg = w / 6;
    const int colbase = blockIdx.x * 64;
    const int kg0 = blockIdx.y * KCHUNK;

    const int frow = tid >> 2;
    const int fq   = (tid & 3) << 2;
    const int slotb = ((fq & 4) << 1) + (fq >> 3);

    const float* xg = g_pooled + (size_t)frow*QDIM + kg0 + fq;
    const float* wg = w0 + (size_t)(colbase + (tid >> 2))*QDIM + kg0 + ((tid & 3) << 2);

    float4 xv = *(const float4*)xg;
    float4 wv = make_float4(0.f,0.f,0.f,0.f);
    if (tid < 256) wv = *(const float4*)wg;

    float acc[4][4] = {};
    const int NT = KCHUNK / 16;
    for (int t = 0; t < NT; t++) {
        unsigned* xsc = xs[t & 1];
        unsigned* wsc = ws[t & 1];
        {
            unsigned* d = xsc + frow*XDP + slotb;
            d[0] = f2tf32(xv.x); d[2] = f2tf32(xv.y);
            d[4] = f2tf32(xv.z); d[6] = f2tf32(xv.w);
        }
        if (tid < 256) {
            unsigned* d = wsc + (tid >> 2)*XDP + slotb;
            d[0] = f2tf32(wv.x); d[2] = f2tf32(wv.y);
            d[4] = f2tf32(wv.z); d[6] = f2tf32(wv.w);
        }
        __syncthreads();
        if (t + 1 < NT) {
            xv = *(const float4*)(xg + (t + 1)*16);
            if (tid < 256) wv = *(const float4*)(wg + (t + 1)*16);
        }
        #pragma unroll
        for (int kt = 0; kt < 2; kt++) {
            uint2 alo = *(const uint2*)(xsc + (rg*16 + gid    )*XDP + kt*8 + tig*2);
            uint2 ahi = *(const uint2*)(xsc + (rg*16 + gid + 8)*XDP + kt*8 + tig*2);
            #pragma unroll
            for (int nt = 0; nt < 4; nt++) {
                uint2 bb = *(const uint2*)(wsc + (cg*32 + nt*8 + gid)*XDP + kt*8 + tig*2);
                mma_tf32(acc[nt], alo.x, ahi.x, alo.y, ahi.y, bb.x, bb.y);
            }
        }
        __syncthreads();
    }
    #pragma unroll
    for (int nt = 0; nt < 4; nt++) {
        int col = colbase + cg*32 + nt*8 + tig*2;
        int row = rg*16 + gid;
        float* pp = g_partial + ((size_t)blockIdx.y*96 + row)*256 + col;
        *(float2*)pp             = make_float2(acc[nt][0], acc[nt][1]);
        *(float2*)(pp + 8*256)   = make_float2(acc[nt][2], acc[nt][3]);
    }
}

// ---------------- kernel E: reduce + relu + 256x256 GEMM + relu ------------
__global__ void __launch_bounds__(256) kE(const float* __restrict__ rb0,
                                          const float* __restrict__ rw1,
                                          const float* __restrict__ rb1,
                                          float* __restrict__ out) {
    __shared__ float h2s[256];
    __shared__ float w1s[256*33];
    const int row = blockIdx.x;
    const int o = threadIdx.x;
    float s = rb0[o];
    #pragma unroll 4
    for (int ks = 0; ks < KSPLIT; ks++)
        s += g_partial[((size_t)ks*96 + row)*256 + o];
    h2s[o] = fmaxf(s, 0.f);
    __syncthreads();

    float acc = rb1[o];
    for (int jt = 0; jt < 256; jt += 32) {
        for (int i = threadIdx.x; i < 8192; i += 256) {
            int oo = i >> 5, jj = i & 31;
            w1s[oo*33 + jj] = rw1[(size_t)oo*256 + jt + jj];
        }
        __syncthreads();
        #pragma unroll
        for (int jj = 0; jj < 32; jj++)
            acc = fmaf(h2s[jt + jj], w1s[o*33 + jj], acc);
        __syncthreads();
    }
    out[(size_t)row*256 + o] = fmaxf(acc, 0.f);
}

// ---------------- launch ----------------
extern "C" void kernel_launch(void* const* d_in, const int* in_sizes, int n_in,
                              void* d_out, int out_size) {
    const float* proposals = (const float*)d_in[0];
    const float* kxyz      = (const float*)d_in[1];
    const float* kfeat     = (const float*)d_in[2];
    const float* gnoise    = (const float*)d_in[3];
    const float* w00 = (const float*)d_in[4];
    const float* b00 = (const float*)d_in[5];
    const float* w01 = (const float*)d_in[6];
    const float* b01 = (const float*)d_in[7];
    const float* w10 = (const float*)d_in[8];
    const float* b10 = (const float*)d_in[9];
    const float* w11 = (const float*)d_in[10];
    const float* b11 = (const float*)d_in[11];
    const float* rw0 = (const float*)d_in[12];
    const float* rb0 = (const float*)d_in[13];
    const float* rw1 = (const float*)d_in[14];
    const float* rb1 = (const float*)d_in[15];
    float* out = (float*)d_out;

    cudaFuncSetAttribute(kC2, cudaFuncAttributeMaxDynamicSharedMemorySize,
                         KC2_SMEM_WORDS * 4);

    kA<<<(NTOT + 255)/256, 256>>>(proposals, gnoise);
    kB<<<dim3(KKEY/32, 4), 256>>>(kfeat, w00, w10);
    kQ<<<NTOT/16, 512>>>(kxyz);
    kC2<<<NTOT/12, 384, KC2_SMEM_WORDS * 4>>>(w00, b00, w01, b01,
                                              w10, b10, w11, b11);
    kD<<<dim3(4, KSPLIT), 384>>>(rw0);
    kE<<<96, 256>>>(rb0, rw1, rb1, out);
}